// round 1
// baseline (speedup 1.0000x reference)
#include <cuda_runtime.h>
#include <math.h>

// Problem constants
constexpr int BB  = 64;      // batch
constexpr int LL  = 2048;    // sequence length
constexpr int DD  = 256;     // channels H
constexpr int NN2 = 32;      // diagonal modes
constexpr int MM  = BB * LL; // 131072 positions

typedef unsigned long long u64;

// ---------------- scratch (__device__ globals; no allocation allowed) --------
__device__ __align__(128) float4 g_wpk[2 * DD * (NN2 / 2)];      // {wr0,wr1,wi0,wi1}
__device__ __align__(128) float4 g_cpk[2 * DD * (NN2 / 2)];      // {cr0,cr1,ci0,ci1}
__device__ __align__(128) float  g_wt [2 * DD * 2 * DD];         // [dir][k=256][n=512]
__device__ __align__(128) float  g_ybuf[(size_t)2 * BB * LL * DD];       // 268 MB
__device__ __align__(128) float  g_zbuf[(size_t)2 * MM * 2 * DD];        // 537 MB

// ---------------- packed f32x2 helpers (Blackwell FFMA2 path) ----------------
__device__ __forceinline__ u64 pk2(float lo, float hi) {
    u64 r; asm("mov.b64 %0, {%1,%2};" : "=l"(r) : "f"(lo), "f"(hi)); return r;
}
__device__ __forceinline__ void upk2(u64 v, float& lo, float& hi) {
    asm("mov.b64 {%0,%1}, %2;" : "=f"(lo), "=f"(hi) : "l"(v));
}
__device__ __forceinline__ u64 fma2(u64 a, u64 b, u64 c) {
    u64 d; asm("fma.rn.f32x2 %0, %1, %2, %3;" : "=l"(d) : "l"(a), "l"(b), "l"(c)); return d;
}
__device__ __forceinline__ u64 mul2(u64 a, u64 b) {
    u64 d; asm("mul.rn.f32x2 %0, %1, %2;" : "=l"(d) : "l"(a), "l"(b)); return d;
}

__device__ __forceinline__ float gelu_exact(float v) {
    return 0.5f * v * (1.0f + erff(v * 0.70710678118654752f));
}
__device__ __forceinline__ float sigm(float v) {
    return 1.0f / (1.0f + expf(-v));
}

// ---------------- kernel 1: precompute discrete-time constants ---------------
__global__ void k_prep(const float* __restrict__ ld0,  const float* __restrict__ cre0,
                       const float* __restrict__ cim0, const float* __restrict__ lar0,
                       const float* __restrict__ aim0,
                       const float* __restrict__ ld1,  const float* __restrict__ cre1,
                       const float* __restrict__ cim1, const float* __restrict__ lar1,
                       const float* __restrict__ aim1)
{
    int i = blockIdx.x * blockDim.x + threadIdx.x;
    if (i >= 2 * DD * NN2) return;
    int d = i / (DD * NN2);
    int r = i % (DD * NN2);
    int h = r / NN2, n = r % NN2;
    const float* ld  = d ? ld1  : ld0;
    const float* cre = d ? cre1 : cre0;
    const float* cim = d ? cim1 : cim0;
    const float* lar = d ? lar1 : lar0;
    const float* aim = d ? aim1 : aim0;

    double dt  = exp((double)ld[h]);
    double Are = -exp((double)lar[h * NN2 + n]);
    double Aim = (double)aim[h * NN2 + n];
    double dre = Are * dt, dim_ = Aim * dt;
    double er  = exp(dre);
    double wr  = er * cos(dim_), wi = er * sin(dim_);
    // F = (exp(dtA)-1)/A  via E * conj(A)/|A|^2
    double Er = wr - 1.0, Ei = wi;
    double den = Are * Are + Aim * Aim;
    double Fr = (Er * Are + Ei * Aim) / den;
    double Fi = (Ei * Are - Er * Aim) / den;
    double c0r = (double)cre[h * NN2 + n], c0i = (double)cim[h * NN2 + n];
    double Cr = 2.0 * (c0r * Fr - c0i * Fi);   // fold the 2*Re(...) factor
    double Ci = 2.0 * (c0r * Fi + c0i * Fr);

    float* wp = (float*)g_wpk;
    float* cp = (float*)g_cpk;
    size_t base = ((size_t)(d * DD + h) * (NN2 / 2) + (n >> 1)) * 4;
    int comp = n & 1;
    wp[base + comp]     = (float)wr;
    wp[base + 2 + comp] = (float)wi;
    cp[base + comp]     = (float)Cr;
    cp[base + 2 + comp] = (float)Ci;
}

// transpose W_glu (512,256) -> g_wt[dir][k][n]
__global__ void k_wt(const float* __restrict__ w0, const float* __restrict__ w1)
{
    int i = blockIdx.x * blockDim.x + threadIdx.x;
    if (i >= 2 * DD * 2 * DD) return;
    int d = i / (DD * 2 * DD);
    int r = i % (DD * 2 * DD);
    int k = r / (2 * DD), n = r % (2 * DD);
    const float* w = d ? w1 : w0;
    g_wt[i] = w[(size_t)n * DD + k];
}

// ---------------- kernel 2: diagonal SSM scan + D-skip + GELU ----------------
// Block = 256 threads: 8 warps; each warp = 4 sequences x 8 lanes; lane = 4 modes
// (2 packed f32x2 pairs). Block covers (dir, batch, 32 channels), scans all L.
__global__ __launch_bounds__(256) void k_scan(const float* __restrict__ x,
                                              const float* __restrict__ ds0,
                                              const float* __restrict__ ds1)
{
    const int d  = blockIdx.z, b = blockIdx.y;
    const int h0 = blockIdx.x * 32;
    const int t  = threadIdx.x;
    const int w  = t >> 5, lane = t & 31;
    const int s_in = lane >> 3, sub = lane & 7;
    const int col = w * 4 + s_in;
    const int h   = h0 + col;

    const float4* wp = &g_wpk[(size_t)(d * DD + h) * (NN2 / 2)];
    const float4* cp = &g_cpk[(size_t)(d * DD + h) * (NN2 / 2)];
    float4 W0 = wp[sub * 2], W1 = wp[sub * 2 + 1];
    float4 C0 = cp[sub * 2], C1 = cp[sub * 2 + 1];
    u64 wr0 = pk2(W0.x, W0.y), wi0 = pk2(W0.z, W0.w), nwi0 = pk2(-W0.z, -W0.w);
    u64 wr1 = pk2(W1.x, W1.y), wi1 = pk2(W1.z, W1.w), nwi1 = pk2(-W1.z, -W1.w);
    u64 cr0 = pk2(C0.x, C0.y), nci0 = pk2(-C0.z, -C0.w);
    u64 cr1 = pk2(C1.x, C1.y), nci1 = pk2(-C1.z, -C1.w);
    const float dsk = (d ? ds1 : ds0)[h];

    u64 sr0 = 0ull, si0 = 0ull, sr1 = 0ull, si1 = 0ull;

    __shared__ __align__(16) float buf[64][32];
    const float* xb = x + (size_t)b * LL * DD;
    float* yb = g_ybuf + ((size_t)d * BB + b) * LL * DD;

    for (int c = 0; c < LL / 64; c++) {
        // ---- stage chunk of input (coalesced; reverse dir reads back-to-front)
        float4 va, vb2;
        {
            int idx = t;           int ir = idx >> 3, c4 = idx & 7;
            int rr = (d == 0) ? (c * 64 + ir) : (LL - 1 - c * 64 - ir);
            va  = *(const float4*)(xb + (size_t)rr * DD + h0 + c4 * 4);
            idx = t + 256;         ir = idx >> 3;     c4 = idx & 7;
            rr = (d == 0) ? (c * 64 + ir) : (LL - 1 - c * 64 - ir);
            vb2 = *(const float4*)(xb + (size_t)rr * DD + h0 + c4 * 4);
        }
        __syncthreads();   // previous writeback done
        {
            int idx = t;       *(float4*)&buf[idx >> 3][(idx & 7) * 4] = va;
            idx = t + 256;     *(float4*)&buf[idx >> 3][(idx & 7) * 4] = vb2;
        }
        __syncthreads();

        // ---- scan 64 steps
        #pragma unroll 8
        for (int i = 0; i < 64; i++) {
            float u = buf[i][col];
            u64 u2 = pk2(u, u);
            u64 t0 = mul2(wi0, sr0);
            sr0 = fma2(wr0, sr0, fma2(nwi0, si0, u2));
            si0 = fma2(wr0, si0, t0);
            u64 t1 = mul2(wi1, sr1);
            sr1 = fma2(wr1, sr1, fma2(nwi1, si1, u2));
            si1 = fma2(wr1, si1, t1);
            u64 acc = mul2(cr0, sr0);
            acc = fma2(nci0, si0, acc);
            acc = fma2(cr1, sr1, acc);
            acc = fma2(nci1, si1, acc);
            float lo, hi; upk2(acc, lo, hi);
            float rsum = lo + hi;
            rsum += __shfl_xor_sync(0xffffffffu, rsum, 1);
            rsum += __shfl_xor_sync(0xffffffffu, rsum, 2);
            rsum += __shfl_xor_sync(0xffffffffu, rsum, 4);
            if (sub == 0) buf[i][col] = fmaf(dsk, u, rsum);
        }
        __syncthreads();

        // ---- GELU + coalesced writeback (rev dir written to original positions)
        #pragma unroll
        for (int j = 0; j < 2; j++) {
            int idx = t + 256 * j;
            int ir = idx >> 3, c4 = idx & 7;
            int rr = (d == 0) ? (c * 64 + ir) : (LL - 1 - c * 64 - ir);
            float4 vv = *(float4*)&buf[ir][c4 * 4];
            vv.x = gelu_exact(vv.x); vv.y = gelu_exact(vv.y);
            vv.z = gelu_exact(vv.z); vv.w = gelu_exact(vv.w);
            *(float4*)(yb + (size_t)rr * DD + h0 + c4 * 4) = vv;
        }
    }
}

// ---------------- kernel 3: z = Y @ W^T + b  (fp32 128x128 tiled GEMM) -------
__global__ __launch_bounds__(256) void k_gemm(const float* __restrict__ bg0,
                                              const float* __restrict__ bg1)
{
    const int d  = blockIdx.z;
    const int n0 = blockIdx.x * 128;
    const size_t m0 = (size_t)blockIdx.y * 128;
    const float* A  = g_ybuf + (size_t)d * BB * LL * DD + m0 * DD;
    const float* Bt = g_wt   + (size_t)d * DD * 2 * DD;
    float* Z = g_zbuf + ((size_t)d * MM + m0) * (2 * DD);

    __shared__ __align__(16) float As[8][128];
    __shared__ __align__(16) float Bs[8][128];
    const int t  = threadIdx.x;
    const int tx = t & 15, ty = t >> 4;
    const int am = t >> 1,  ak4 = (t & 1) * 4;
    const int bk = t >> 5,  bn4 = (t & 31) * 4;

    float acc[8][8];
    #pragma unroll
    for (int i = 0; i < 8; i++)
        #pragma unroll
        for (int j = 0; j < 8; j++) acc[i][j] = 0.0f;

    for (int k0 = 0; k0 < DD; k0 += 8) {
        float4 av = *(const float4*)(A  + (size_t)am * DD + k0 + ak4);
        float4 bv = *(const float4*)(Bt + (size_t)(k0 + bk) * (2 * DD) + n0 + bn4);
        __syncthreads();
        As[ak4 + 0][am] = av.x; As[ak4 + 1][am] = av.y;
        As[ak4 + 2][am] = av.z; As[ak4 + 3][am] = av.w;
        *(float4*)&Bs[bk][bn4] = bv;
        __syncthreads();
        #pragma unroll
        for (int kk = 0; kk < 8; kk++) {
            float a[8], bb[8];
            *(float4*)&a[0]  = *(float4*)&As[kk][ty * 8];
            *(float4*)&a[4]  = *(float4*)&As[kk][ty * 8 + 4];
            *(float4*)&bb[0] = *(float4*)&Bs[kk][tx * 8];
            *(float4*)&bb[4] = *(float4*)&Bs[kk][tx * 8 + 4];
            #pragma unroll
            for (int i = 0; i < 8; i++)
                #pragma unroll
                for (int j = 0; j < 8; j++)
                    acc[i][j] = fmaf(a[i], bb[j], acc[i][j]);
        }
    }

    const float* bg = d ? bg1 : bg0;
    float bias[8];
    #pragma unroll
    for (int j = 0; j < 8; j++) bias[j] = bg[n0 + tx * 8 + j];
    #pragma unroll
    for (int i = 0; i < 8; i++) {
        float4 o0, o1;
        o0.x = acc[i][0] + bias[0]; o0.y = acc[i][1] + bias[1];
        o0.z = acc[i][2] + bias[2]; o0.w = acc[i][3] + bias[3];
        o1.x = acc[i][4] + bias[4]; o1.y = acc[i][5] + bias[5];
        o1.z = acc[i][6] + bias[6]; o1.w = acc[i][7] + bias[7];
        float* zr = Z + (size_t)(ty * 8 + i) * (2 * DD) + n0 + tx * 8;
        *(float4*)zr       = o0;
        *(float4*)(zr + 4) = o1;
    }
}

// ---------------- kernel 4: GLU epilogue, fuse both directions ----------------
__global__ __launch_bounds__(256) void k_glu(float* __restrict__ out)
{
    size_t i4 = (size_t)blockIdx.x * blockDim.x + threadIdx.x;  // one float4 each
    size_t m = i4 >> 6;
    int    q = (int)(i4 & 63);
    const float* zf = g_zbuf + m * (2 * DD);
    const float* zr = g_zbuf + (size_t)MM * (2 * DD) + m * (2 * DD);
    float4 a1 = *(const float4*)(zf + q * 4);
    float4 a2 = *(const float4*)(zf + DD + q * 4);
    float4 b1 = *(const float4*)(zr + q * 4);
    float4 b2 = *(const float4*)(zr + DD + q * 4);
    float4 o;
    o.x = a1.x * sigm(a2.x) + b1.x * sigm(b2.x);
    o.y = a1.y * sigm(a2.y) + b1.y * sigm(b2.y);
    o.z = a1.z * sigm(a2.z) + b1.z * sigm(b2.z);
    o.w = a1.w * sigm(a2.w) + b1.w * sigm(b2.w);
    *(float4*)(out + m * DD + q * 4) = o;
}

// ---------------- launch ------------------------------------------------------
extern "C" void kernel_launch(void* const* d_in, const int* in_sizes, int n_in,
                              void* d_out, int out_size)
{
    const float* x    = (const float*)d_in[0];
    const float* ld0  = (const float*)d_in[1];
    const float* cre0 = (const float*)d_in[2];
    const float* cim0 = (const float*)d_in[3];
    const float* lar0 = (const float*)d_in[4];
    const float* aim0 = (const float*)d_in[5];
    const float* ds0  = (const float*)d_in[6];
    const float* wg0  = (const float*)d_in[7];
    const float* bg0  = (const float*)d_in[8];
    const float* ld1  = (const float*)d_in[9];
    const float* cre1 = (const float*)d_in[10];
    const float* cim1 = (const float*)d_in[11];
    const float* lar1 = (const float*)d_in[12];
    const float* aim1 = (const float*)d_in[13];
    const float* ds1  = (const float*)d_in[14];
    const float* wg1  = (const float*)d_in[15];
    const float* bg1  = (const float*)d_in[16];
    float* out = (float*)d_out;

    k_prep<<<(2 * DD * NN2 + 255) / 256, 256>>>(ld0, cre0, cim0, lar0, aim0,
                                                ld1, cre1, cim1, lar1, aim1);
    k_wt<<<(2 * DD * 2 * DD + 255) / 256, 256>>>(wg0, wg1);
    k_scan<<<dim3(DD / 32, BB, 2), 256>>>(x, ds0, ds1);
    k_gemm<<<dim3(2 * DD / 128, MM / 128, 2), 256>>>(bg0, bg1);
    k_glu<<<(size_t)MM * DD / 4 / 256, 256>>>(out);
}

// round 3
// speedup vs baseline: 1.6494x; 1.6494x over previous
#include <cuda_runtime.h>
#include <cuda_bf16.h>
#include <math.h>
#include <cstdint>

// Problem constants
constexpr int BB  = 64;      // batch
constexpr int LL  = 2048;    // sequence length
constexpr int DD  = 256;     // channels H
constexpr int NN2 = 32;      // diagonal modes
constexpr int MM  = BB * LL; // 131072 positions

typedef unsigned long long u64;

// ---------------- scratch (__device__ globals; no allocation allowed) --------
__device__ __align__(128) float4 g_wpk[2 * DD * (NN2 / 2)];
__device__ __align__(128) float4 g_cpk[2 * DD * (NN2 / 2)];
__device__ __align__(128) __nv_bfloat16 g_yh[(size_t)2 * MM * DD];   // 134 MB
__device__ __align__(128) __nv_bfloat16 g_yl[(size_t)2 * MM * DD];   // 134 MB
__device__ __align__(128) __nv_bfloat16 g_wbh[2 * 2 * DD * DD];      // reordered W hi
__device__ __align__(128) __nv_bfloat16 g_wbl[2 * 2 * DD * DD];      // reordered W lo
__device__ __align__(128) float g_bias2[2 * 2 * DD];                 // reordered bias

// ---------------- packed f32x2 helpers ---------------------------------------
__device__ __forceinline__ u64 pk2(float lo, float hi) {
    u64 r; asm("mov.b64 %0, {%1,%2};" : "=l"(r) : "f"(lo), "f"(hi)); return r;
}
__device__ __forceinline__ void upk2(u64 v, float& lo, float& hi) {
    asm("mov.b64 {%0,%1}, %2;" : "=f"(lo), "=f"(hi) : "l"(v));
}
__device__ __forceinline__ u64 fma2(u64 a, u64 b, u64 c) {
    u64 d; asm("fma.rn.f32x2 %0, %1, %2, %3;" : "=l"(d) : "l"(a), "l"(b), "l"(c)); return d;
}
__device__ __forceinline__ u64 mul2(u64 a, u64 b) {
    u64 d; asm("mul.rn.f32x2 %0, %1, %2;" : "=l"(d) : "l"(a), "l"(b)); return d;
}
__device__ __forceinline__ float gelu_exact(float v) {
    return 0.5f * v * (1.0f + erff(v * 0.70710678118654752f));
}
__device__ __forceinline__ float sigm(float v) {
    return 1.0f / (1.0f + expf(-v));
}

// ---------------- smem / async helpers ----------------------------------------
__device__ __forceinline__ uint32_t smem_u32(const void* p) {
    uint32_t a;
    asm("{ .reg .u64 t; cvta.to.shared.u64 t, %1; cvt.u32.u64 %0, t; }" : "=r"(a) : "l"(p));
    return a;
}
// SW128-style swizzle on (row*128 + seg*16) offsets
__device__ __forceinline__ uint32_t swz(uint32_t o) { return o ^ ((o >> 3) & 0x70); }

__device__ __forceinline__ void cpa16(uint32_t dst, const void* src) {
    asm volatile("cp.async.cg.shared.global [%0], [%1], 16;" :: "r"(dst), "l"(src));
}

#define LDM4(r, addr) \
    asm volatile("ldmatrix.sync.aligned.m8n8.x4.shared.b16 {%0,%1,%2,%3}, [%4];" \
        : "=r"((r)[0]), "=r"((r)[1]), "=r"((r)[2]), "=r"((r)[3]) : "r"(addr))

#define MMA16816(c, a, b0, b1) \
    asm volatile("mma.sync.aligned.m16n8k16.row.col.f32.bf16.bf16.f32 " \
        "{%0,%1,%2,%3}, {%4,%5,%6,%7}, {%8,%9}, {%0,%1,%2,%3};" \
        : "+f"((c)[0]), "+f"((c)[1]), "+f"((c)[2]), "+f"((c)[3]) \
        : "r"((a)[0]), "r"((a)[1]), "r"((a)[2]), "r"((a)[3]), "r"(b0), "r"(b1))

// ---------------- kernel 1: precompute discrete-time constants ---------------
__global__ void k_prep(const float* __restrict__ ld0,  const float* __restrict__ cre0,
                       const float* __restrict__ cim0, const float* __restrict__ lar0,
                       const float* __restrict__ aim0,
                       const float* __restrict__ ld1,  const float* __restrict__ cre1,
                       const float* __restrict__ cim1, const float* __restrict__ lar1,
                       const float* __restrict__ aim1)
{
    int i = blockIdx.x * blockDim.x + threadIdx.x;
    if (i >= 2 * DD * NN2) return;
    int d = i / (DD * NN2);
    int r = i % (DD * NN2);
    int h = r / NN2, n = r % NN2;
    const float* ld  = d ? ld1  : ld0;
    const float* cre = d ? cre1 : cre0;
    const float* cim = d ? cim1 : cim0;
    const float* lar = d ? lar1 : lar0;
    const float* aim = d ? aim1 : aim0;

    double dt  = exp((double)ld[h]);
    double Are = -exp((double)lar[h * NN2 + n]);
    double Aim = (double)aim[h * NN2 + n];
    double dre = Are * dt, dim_ = Aim * dt;
    double er  = exp(dre);
    double wr  = er * cos(dim_), wi = er * sin(dim_);
    double Er = wr - 1.0, Ei = wi;
    double den = Are * Are + Aim * Aim;
    double Fr = (Er * Are + Ei * Aim) / den;
    double Fi = (Ei * Are - Er * Aim) / den;
    double c0r = (double)cre[h * NN2 + n], c0i = (double)cim[h * NN2 + n];
    double Cr = 2.0 * (c0r * Fr - c0i * Fi);
    double Ci = 2.0 * (c0r * Fi + c0i * Fr);

    float* wp = (float*)g_wpk;
    float* cp = (float*)g_cpk;
    size_t base = ((size_t)(d * DD + h) * (NN2 / 2) + (n >> 1)) * 4;
    int comp = n & 1;
    wp[base + comp]     = (float)wr;
    wp[base + 2 + comp] = (float)wi;
    cp[base + comp]     = (float)Cr;
    cp[base + 2 + comp] = (float)Ci;
}

// ---------------- kernel 1b: reorder + bf16-split the GLU weights ------------
// New row r: r=2j   -> orig row j       (linear half)
//            r=2j+1 -> orig row j+256   (gate half)
__global__ void k_wt(const float* __restrict__ w0, const float* __restrict__ w1,
                     const float* __restrict__ b0, const float* __restrict__ b1)
{
    int i = blockIdx.x * blockDim.x + threadIdx.x;
    if (i >= 2 * 2 * DD * DD) return;
    int d = i / (2 * DD * DD);
    int rem = i % (2 * DD * DD);
    int r = rem / DD, k = rem % DD;
    int o = (r & 1) ? (r >> 1) + DD : (r >> 1);
    const float* w = d ? w1 : w0;
    float v = w[(size_t)o * DD + k];
    __nv_bfloat16 hi = __float2bfloat16(v);
    float lof = v - __bfloat162float(hi);
    g_wbh[i] = hi;
    g_wbl[i] = __float2bfloat16(lof);
    if (k == 0) g_bias2[d * 2 * DD + r] = (d ? b1 : b0)[o];
}

// ---------------- kernel 2: diagonal SSM scan + D-skip + GELU ----------------
__global__ __launch_bounds__(256) void k_scan(const float* __restrict__ x,
                                              const float* __restrict__ ds0,
                                              const float* __restrict__ ds1)
{
    const int d  = blockIdx.z, b = blockIdx.y;
    const int h0 = blockIdx.x * 32;
    const int t  = threadIdx.x;
    const int w  = t >> 5, lane = t & 31;
    const int s_in = lane >> 3, sub = lane & 7;
    const int col = w * 4 + s_in;
    const int h   = h0 + col;

    const float4* wp = &g_wpk[(size_t)(d * DD + h) * (NN2 / 2)];
    const float4* cp = &g_cpk[(size_t)(d * DD + h) * (NN2 / 2)];
    float4 W0 = wp[sub * 2], W1 = wp[sub * 2 + 1];
    float4 C0 = cp[sub * 2], C1 = cp[sub * 2 + 1];
    u64 wr0 = pk2(W0.x, W0.y), wi0 = pk2(W0.z, W0.w), nwi0 = pk2(-W0.z, -W0.w);
    u64 wr1 = pk2(W1.x, W1.y), wi1 = pk2(W1.z, W1.w), nwi1 = pk2(-W1.z, -W1.w);
    u64 cr0 = pk2(C0.x, C0.y), nci0 = pk2(-C0.z, -C0.w);
    u64 cr1 = pk2(C1.x, C1.y), nci1 = pk2(-C1.z, -C1.w);
    const float dsk = (d ? ds1 : ds0)[h];

    u64 sr0 = 0ull, si0 = 0ull, sr1 = 0ull, si1 = 0ull;

    __shared__ __align__(16) float buf[64][32];
    const float* xb = x + (size_t)b * LL * DD;
    const size_t mbase = ((size_t)d * BB + b) * LL;

    for (int c = 0; c < LL / 64; c++) {
        float4 va, vb2;
        {
            int idx = t;           int ir = idx >> 3, c4 = idx & 7;
            int rr = (d == 0) ? (c * 64 + ir) : (LL - 1 - c * 64 - ir);
            va  = *(const float4*)(xb + (size_t)rr * DD + h0 + c4 * 4);
            idx = t + 256;         ir = idx >> 3;     c4 = idx & 7;
            rr = (d == 0) ? (c * 64 + ir) : (LL - 1 - c * 64 - ir);
            vb2 = *(const float4*)(xb + (size_t)rr * DD + h0 + c4 * 4);
        }
        __syncthreads();
        {
            int idx = t;       *(float4*)&buf[idx >> 3][(idx & 7) * 4] = va;
            idx = t + 256;     *(float4*)&buf[idx >> 3][(idx & 7) * 4] = vb2;
        }
        __syncthreads();

        #pragma unroll 8
        for (int i = 0; i < 64; i++) {
            float u = buf[i][col];
            u64 u2 = pk2(u, u);
            u64 t0 = mul2(wi0, sr0);
            sr0 = fma2(wr0, sr0, fma2(nwi0, si0, u2));
            si0 = fma2(wr0, si0, t0);
            u64 t1 = mul2(wi1, sr1);
            sr1 = fma2(wr1, sr1, fma2(nwi1, si1, u2));
            si1 = fma2(wr1, si1, t1);
            u64 acc = mul2(cr0, sr0);
            acc = fma2(nci0, si0, acc);
            acc = fma2(cr1, sr1, acc);
            acc = fma2(nci1, si1, acc);
            float lo, hi; upk2(acc, lo, hi);
            float rsum = lo + hi;
            rsum += __shfl_xor_sync(0xffffffffu, rsum, 1);
            rsum += __shfl_xor_sync(0xffffffffu, rsum, 2);
            rsum += __shfl_xor_sync(0xffffffffu, rsum, 4);
            if (sub == 0) buf[i][col] = fmaf(dsk, u, rsum);
        }
        __syncthreads();

        // GELU + bf16 hi/lo split writeback
        #pragma unroll
        for (int j = 0; j < 2; j++) {
            int idx = t + 256 * j;
            int ir = idx >> 3, c4 = idx & 7;
            int rr = (d == 0) ? (c * 64 + ir) : (LL - 1 - c * 64 - ir);
            float4 vv = *(float4*)&buf[ir][c4 * 4];
            vv.x = gelu_exact(vv.x); vv.y = gelu_exact(vv.y);
            vv.z = gelu_exact(vv.z); vv.w = gelu_exact(vv.w);
            __nv_bfloat162 h01 = __floats2bfloat162_rn(vv.x, vv.y);
            __nv_bfloat162 h23 = __floats2bfloat162_rn(vv.z, vv.w);
            float2 f01 = __bfloat1622float2(h01);
            float2 f23 = __bfloat1622float2(h23);
            __nv_bfloat162 l01 = __floats2bfloat162_rn(vv.x - f01.x, vv.y - f01.y);
            __nv_bfloat162 l23 = __floats2bfloat162_rn(vv.z - f23.x, vv.w - f23.y);
            size_t base = (mbase + rr) * DD + h0 + c4 * 4;
            uint2 uh, ul;
            uh.x = *(uint32_t*)&h01; uh.y = *(uint32_t*)&h23;
            ul.x = *(uint32_t*)&l01; ul.y = *(uint32_t*)&l23;
            *(uint2*)&g_yh[base] = uh;
            *(uint2*)&g_yl[base] = ul;
        }
    }
}

// ---------------- kernel 3: mma.sync bf16-split GEMM + fused GLU epilogue ----
// CTA: 128(M) x 128(N); 8 warps of 64x32; K' = 768 over 12 chunks of 64:
// chunks 0-3: Ah*Bh, 4-7: Ah*Bl, 8-11: Al*Bh. Both dirs sequential per CTA.
static constexpr int STAGE_BYTES = 32768;          // 16KB A + 16KB B
static constexpr int SM_TOTAL    = 3 * STAGE_BYTES; // 96KB

__device__ __forceinline__ void load_chunk(uint32_t stage_base, int dir, int c,
                                           size_t m0, int n0, int t)
{
    const __nv_bfloat16* ya = (c < 8) ? g_yh : g_yl;
    const __nv_bfloat16* asrc = ya + ((size_t)dir * MM + m0) * DD + (c & 3) * 64;
    #pragma unroll
    for (int j = 0; j < 4; j++) {
        int idx = t + 256 * j;
        int row = idx >> 3, seg = idx & 7;
        cpa16(stage_base + swz(row * 128 + seg * 16), asrc + (size_t)row * DD + seg * 8);
    }
    const __nv_bfloat16* wb = (((c >> 2) & 3) == 1) ? g_wbl : g_wbh;
    const __nv_bfloat16* bsrc = wb + (size_t)dir * 2 * DD * DD + (size_t)n0 * DD + (c & 3) * 64;
    #pragma unroll
    for (int j = 0; j < 4; j++) {
        int idx = t + 256 * j;
        int row = idx >> 3, seg = idx & 7;
        cpa16(stage_base + 16384 + swz(row * 128 + seg * 16), bsrc + (size_t)row * DD + seg * 8);
    }
    asm volatile("cp.async.commit_group;" ::: "memory");
}

__global__ __launch_bounds__(256, 1) void k_mm2(float* __restrict__ out)
{
    extern __shared__ __align__(1024) char smem[];
    uint32_t sb = smem_u32(smem);
    const int t = threadIdx.x;
    const int lane = t & 31, w = t >> 5;
    const int mw = (w >> 2) * 64, nw = (w & 3) * 32;
    const int n0 = blockIdx.x * 128;
    const size_t m0 = (size_t)blockIdx.y * 128;

    // per-lane ldmatrix relative addresses (row*128 part; swizzle xor = (row&7)*16)
    const uint32_t xorv = (lane & 7) * 16;
    uint32_t relA[4], relB[2];
    #pragma unroll
    for (int i = 0; i < 4; i++)
        relA[i] = (uint32_t)(mw + i * 16 + (lane & 15)) * 128;
    #pragma unroll
    for (int p = 0; p < 2; p++)
        relB[p] = 16384u + (uint32_t)(nw + p * 16 + ((lane >> 4) << 3) + (lane & 7)) * 128;
    const uint32_t hsegA = (uint32_t)(lane >> 4);
    const uint32_t hsegB = (uint32_t)((lane >> 3) & 1);

    float acc[4][4][4];
    float oacc[4][4][2];
    #pragma unroll
    for (int i = 0; i < 4; i++)
        #pragma unroll
        for (int j = 0; j < 4; j++) { oacc[i][j][0] = 0.f; oacc[i][j][1] = 0.f; }

    for (int dir = 0; dir < 2; dir++) {
        #pragma unroll
        for (int i = 0; i < 4; i++)
            #pragma unroll
            for (int j = 0; j < 4; j++)
                #pragma unroll
                for (int q = 0; q < 4; q++) acc[i][j][q] = 0.f;

        load_chunk(sb + 0 * STAGE_BYTES, dir, 0, m0, n0, t);
        load_chunk(sb + 1 * STAGE_BYTES, dir, 1, m0, n0, t);
        load_chunk(sb + 2 * STAGE_BYTES, dir, 2, m0, n0, t);

        for (int c = 0; c < 12; c++) {
            if (c <= 9)       asm volatile("cp.async.wait_group 2;" ::: "memory");
            else if (c == 10) asm volatile("cp.async.wait_group 1;" ::: "memory");
            else              asm volatile("cp.async.wait_group 0;" ::: "memory");
            __syncthreads();

            uint32_t base = sb + (uint32_t)(c % 3) * STAGE_BYTES;
            #pragma unroll
            for (int kk = 0; kk < 4; kk++) {
                uint32_t soffA = (((uint32_t)(2 * kk) + hsegA) * 16) ^ xorv;
                uint32_t soffB = (((uint32_t)(2 * kk) + hsegB) * 16) ^ xorv;
                uint32_t afr[4][4], bfr[2][4];
                #pragma unroll
                for (int i = 0; i < 4; i++) LDM4(afr[i], base + relA[i] + soffA);
                #pragma unroll
                for (int p = 0; p < 2; p++) LDM4(bfr[p], base + relB[p] + soffB);
                #pragma unroll
                for (int i = 0; i < 4; i++)
                    #pragma unroll
                    for (int j = 0; j < 4; j++)
                        MMA16816(acc[i][j], afr[i], bfr[j >> 1][(j & 1) * 2],
                                 bfr[j >> 1][(j & 1) * 2 + 1]);
            }
            __syncthreads();
            if (c + 3 < 12) load_chunk(base, dir, c + 3, m0, n0, t);
        }

        // fused GLU: columns interleaved (even=linear, odd=gate) -> thread-local
        #pragma unroll
        for (int i = 0; i < 4; i++)
            #pragma unroll
            for (int j = 0; j < 4; j++) {
                int nl = nw + 8 * j + 2 * (lane & 3);
                float bl = g_bias2[dir * 512 + n0 + nl];
                float bg = g_bias2[dir * 512 + n0 + nl + 1];
                oacc[i][j][0] += (acc[i][j][0] + bl) * sigm(acc[i][j][1] + bg);
                oacc[i][j][1] += (acc[i][j][2] + bl) * sigm(acc[i][j][3] + bg);
            }
    }

    // write out: ch = (n0 + nl)/2
    const int q = lane >> 2;
    const int chb = (n0 + nw) / 2 + (lane & 3);
    #pragma unroll
    for (int i = 0; i < 4; i++)
        #pragma unroll
        for (int s = 0; s < 2; s++) {
            size_t m = m0 + mw + 16 * i + q + 8 * s;
            float* dst = out + m * DD + chb;
            #pragma unroll
            for (int j = 0; j < 4; j++) dst[4 * j] = oacc[i][j][s];
        }
}

// ---------------- launch ------------------------------------------------------
extern "C" void kernel_launch(void* const* d_in, const int* in_sizes, int n_in,
                              void* d_out, int out_size)
{
    const float* x    = (const float*)d_in[0];
    const float* ld0  = (const float*)d_in[1];
    const float* cre0 = (const float*)d_in[2];
    const float* cim0 = (const float*)d_in[3];
    const float* lar0 = (const float*)d_in[4];
    const float* aim0 = (const float*)d_in[5];
    const float* ds0  = (const float*)d_in[6];
    const float* wg0  = (const float*)d_in[7];
    const float* bg0  = (const float*)d_in[8];
    const float* ld1  = (const float*)d_in[9];
    const float* cre1 = (const float*)d_in[10];
    const float* cim1 = (const float*)d_in[11];
    const float* lar1 = (const float*)d_in[12];
    const float* aim1 = (const float*)d_in[13];
    const float* ds1  = (const float*)d_in[14];
    const float* wg1  = (const float*)d_in[15];
    const float* bg1  = (const float*)d_in[16];
    float* out = (float*)d_out;

    static bool attr_done = false;
    if (!attr_done) {
        cudaFuncSetAttribute(k_mm2, cudaFuncAttributeMaxDynamicSharedMemorySize, SM_TOTAL);
        attr_done = true;
    }

    k_prep<<<(2 * DD * NN2 + 255) / 256, 256>>>(ld0, cre0, cim0, lar0, aim0,
                                                ld1, cre1, cim1, lar1, aim1);
    k_wt<<<(2 * 2 * DD * DD + 255) / 256, 256>>>(wg0, wg1, bg0, bg1);
    k_scan<<<dim3(DD / 32, BB, 2), 256>>>(x, ds0, ds1);
    k_mm2<<<dim3(4, MM / 128), 256, SM_TOTAL>>>(out);
}